// round 13
// baseline (speedup 1.0000x reference)
#include <cuda_runtime.h>
#include <cuda_bf16.h>
#include <cstdint>

#define D       256
#define Kc      1024
#define NROWS   32768
#define Z_ELEMS 8388608
#define CAP     32
#define ASTRIDE 264          // bf16 row stride in smem (256 + 8 pad -> 528B rows)
#define TILE_B  67584        // 128 rows * 528 B

typedef unsigned int u32;
typedef unsigned long long u64;
typedef unsigned short u16;

// ---------------- device globals (no cudaMalloc allowed) -------------------
__device__ float g_cnorm[Kc];
__device__ float g_cnpart[128];
__device__ float g_znorm[NROWS];
__device__ float g_loss;
__device__ unsigned g_done;
__device__ uint4 g_cbbf4[Kc * 32];       // bf16(cb), [k][256] row-major (512B/row)
__device__ u16   g_cand[NROWS * CAP];
__device__ unsigned char g_ccnt[NROWS];

// ---------------- helpers --------------------------------------------------
__device__ __forceinline__ u32 smem_u32(const void* p) {
    u32 a; asm("{ .reg .u64 t; cvta.to.shared.u64 t, %1; cvt.u32.u64 %0, t; }" : "=r"(a) : "l"(p));
    return a;
}
__device__ __forceinline__ void ldsm4(u32* r, u32 addr) {
    asm volatile("ldmatrix.sync.aligned.m8n8.x4.shared.b16 {%0,%1,%2,%3}, [%4];"
        : "=r"(r[0]), "=r"(r[1]), "=r"(r[2]), "=r"(r[3]) : "r"(addr));
}
__device__ __forceinline__ void mma16816(float* c, const u32* a, u32 b0, u32 b1) {
    asm volatile("mma.sync.aligned.m16n8k16.row.col.f32.bf16.bf16.f32 "
        "{%0,%1,%2,%3}, {%4,%5,%6,%7}, {%8,%9}, {%0,%1,%2,%3};"
        : "+f"(c[0]), "+f"(c[1]), "+f"(c[2]), "+f"(c[3])
        : "r"(a[0]), "r"(a[1]), "r"(a[2]), "r"(a[3]), "r"(b0), "r"(b1));
}
__device__ __forceinline__ void cpasync16(u32 dst, const void* src) {
    asm volatile("cp.async.cg.shared.global [%0], [%1], 16;" :: "r"(dst), "l"(src));
}
__device__ __forceinline__ void cpcommit() {
    asm volatile("cp.async.commit_group;" ::: "memory");
}
__device__ __forceinline__ void cpwait0() {
    asm volatile("cp.async.wait_group 0;" ::: "memory");
}
__device__ __forceinline__ int f2ord(float f) {
    int i = __float_as_int(f);
    return i >= 0 ? i : i ^ 0x7FFFFFFF;
}
__device__ __forceinline__ float ord2f(int i) {
    return __int_as_float(i >= 0 ? i : i ^ 0x7FFFFFFF);
}
// unsigned monotone key for lexicographic (score, code) minimum
__device__ __forceinline__ u64 skey(float sc, int code) {
    u32 o = (u32)f2ord(sc) ^ 0x80000000u;
    return ((u64)o << 32) | (u32)code;
}

// ---------------------------------------------------------------------------
// k0: warp-per-code prep. grid 128 x 128 (8 codes/block). Warp loads its code
// row coalesced into smem + converts to bf16 (uint4 stores); lane 0 runs the
// bit-exact sequential unfused norm chain. Per-block max -> g_cnpart[128].
// ---------------------------------------------------------------------------
__global__ void __launch_bounds__(128)
prep_kernel(const float* __restrict__ cb) {
    __shared__ float stage[4][264];        // one row per warp, padded
    __shared__ float nrm[4];
    const int t    = threadIdx.x;
    const int lane = t & 31;
    const int w    = t >> 5;               // warp 0..3
    // two codes per warp (8 codes per block, 2 passes)
    float blkmax = 0.0f;
    #pragma unroll
    for (int pass = 0; pass < 2; ++pass) {
        int c = blockIdx.x * 8 + pass * 4 + w;
        const float* row = cb + (size_t)c * D;
        float4 v0[2];
        u16 pk[8];
        #pragma unroll
        for (int h = 0; h < 2; ++h) {
            v0[h] = *(const float4*)&row[lane * 8 + h * 4];
            __nv_bfloat16 b0 = __float2bfloat16(v0[h].x);
            __nv_bfloat16 b1 = __float2bfloat16(v0[h].y);
            __nv_bfloat16 b2 = __float2bfloat16(v0[h].z);
            __nv_bfloat16 b3 = __float2bfloat16(v0[h].w);
            pk[h * 4 + 0] = *(u16*)&b0; pk[h * 4 + 1] = *(u16*)&b1;
            pk[h * 4 + 2] = *(u16*)&b2; pk[h * 4 + 3] = *(u16*)&b3;
            *(float4*)&stage[w][lane * 8 + h * 4] = v0[h];
        }
        // bf16 row store: 16B per lane = 512B per warp instruction, coalesced
        g_cbbf4[(size_t)c * 32 + lane] = *(uint4*)pk;
        __syncwarp();
        if (lane == 0) {
            float s = 0.0f;
            #pragma unroll 8
            for (int d = 0; d < D; ++d) {
                float v = stage[w][d];
                s = __fadd_rn(s, __fmul_rn(v, v));   // sequential ascending d, unfused
            }
            g_cnorm[c] = s;
            nrm[w] = (pass == 0) ? s : fmaxf(nrm[w], s);
        }
        __syncwarp();
    }
    __syncthreads();
    if (t == 0) {
        blkmax = fmaxf(fmaxf(nrm[0], nrm[1]), fmaxf(nrm[2], nrm[3]));
        g_cnpart[blockIdx.x] = blkmax;
    }
}

// ---------------------------------------------------------------------------
// k1: mma.sync bf16 GEMM + candidate filter (validated R12 form: 8 warps,
// cp.async double-buffered B, register-double-buffered k-loop, barrier-free
// conservative filter -> superset of exact argmin + quantized ties).
// ---------------------------------------------------------------------------
__global__ void __launch_bounds__(256, 1)
mma_cand_kernel(const float* __restrict__ z) {
    extern __shared__ char smr[];
    u16*   Asm    = (u16*)smr;                         // [128][264]
    float* cn_s   = (float*)(smr + 3 * TILE_B);        // [1024]
    float* marg_s = cn_s + 1024;                       // [128]
    int*   rmin_s = (int*)(marg_s + 128);              // [128]
    int*   cnt_s  = rmin_s + 128;                      // [128]
    u16*   cand_s = (u16*)(cnt_s + 128);               // [128][CAP]

    const int t      = threadIdx.x;
    const int lane   = t & 31;
    const int wid    = t >> 5;
    const int warp_m = wid & 3;     // 32-row group
    const int warp_n = wid >> 2;    // 64-code group
    const int gid    = lane >> 2;
    const int tig    = lane & 3;
    const int n0     = blockIdx.x * 128;

    const u32 Abase = smem_u32(Asm);
    const u32 Bbase = Abase + TILE_B;

    {   // prefetch B tile 0
        const char* src = ((const char*)g_cbbf4);
        for (int i = t; i < 4096; i += 256) {
            int r = i >> 5, c = i & 31;
            cpasync16(Bbase + (u32)(r * 528 + c * 16), src + r * 512 + c * 16);
        }
        cpcommit();
    }

    // ---- prologue: A conversion + exact znorm (threads<128); cn (others) ----
    if (t < 128) {
        const int b  = n0 >> 10;
        const int hw = (n0 & 1023) + t;
        const float* zb = z + (size_t)b * (D * 1024) + hw;
        float s = 0.0f;
        for (int d0 = 0; d0 < D; d0 += 8) {
            u16 pk[8];
            #pragma unroll
            for (int i = 0; i < 8; ++i) {
                float v = zb[(size_t)(d0 + i) * 1024];
                s = __fadd_rn(s, __fmul_rn(v, v));      // exact sequential ascending d
                __nv_bfloat16 h = __float2bfloat16(-2.0f * v);
                pk[i] = *(u16*)&h;
            }
            *(uint4*)&Asm[t * ASTRIDE + d0] = *(uint4*)pk;
        }
        g_znorm[n0 + t] = s;
        float cm = 0.0f;
        #pragma unroll 8
        for (int p = 0; p < 128; ++p) cm = fmaxf(cm, g_cnpart[p]);
        marg_s[t] = 0.015625f * sqrtf(s * cm) + 3e-4f;
        rmin_s[t] = 0x7F800000;
        cnt_s[t]  = 0;
    } else {
        for (int i = t - 128; i < Kc; i += 128) cn_s[i] = g_cnorm[i];
    }

    float rm[4] = {3.4e38f, 3.4e38f, 3.4e38f, 3.4e38f};
    int   rowv[4];
    #pragma unroll
    for (int r4 = 0; r4 < 4; ++r4)
        rowv[r4] = warp_m * 32 + (r4 >> 1) * 16 + (r4 & 1) * 8 + gid;

    const int ar = warp_m * 32 + (lane & 15);
    const int ak = (lane >> 4) << 3;
    const int bc = warp_n * 64 + ((lane >> 4) & 1) * 8 + (lane & 7);
    const int bk = ((lane >> 3) & 1) * 8;

    for (int nt = 0; nt < 8; ++nt) {
        cpwait0();
        __syncthreads();   // B[nt] visible; prior stage fully consumed
        if (nt < 7) {      // prefetch B[nt+1]
            const char* src = ((const char*)g_cbbf4) + (size_t)(nt + 1) * 128 * 512;
            u32 dstb = Bbase + (u32)(((nt + 1) & 1) * TILE_B);
            for (int i = t; i < 4096; i += 256) {
                int r = i >> 5, c = i & 31;
                cpasync16(dstb + (u32)(r * 528 + c * 16), src + r * 512 + c * 16);
            }
            cpcommit();
        }
        const u32 Bb = Bbase + (u32)((nt & 1) * TILE_B);

        float acc[2][8][4];
        #pragma unroll
        for (int mt = 0; mt < 2; ++mt)
            #pragma unroll
            for (int j = 0; j < 8; ++j)
                #pragma unroll
                for (int c = 0; c < 4; ++c) acc[mt][j][c] = 0.0f;

        // ---- register double-buffered k-loop ----
        u32 af[2][2][4], bf[2][2][4], bg[2][2][4];
        #pragma unroll
        for (int mt = 0; mt < 2; ++mt)
            ldsm4(af[0][mt], Abase + (u32)(((ar + mt * 16) * ASTRIDE + ak) * 2));
        #pragma unroll
        for (int p = 0; p < 2; ++p) {
            ldsm4(bf[0][p], Bb + (u32)(((bc + p * 16) * ASTRIDE + bk) * 2));
            ldsm4(bg[0][p], Bb + (u32)(((bc + (p + 2) * 16) * ASTRIDE + bk) * 2));
        }
        #pragma unroll
        for (int kk = 0; kk < 16; ++kk) {
            const int cur = kk & 1, nxt = cur ^ 1;
            if (kk < 15) {
                int ko = (kk + 1) * 16;
                #pragma unroll
                for (int mt = 0; mt < 2; ++mt)
                    ldsm4(af[nxt][mt], Abase + (u32)(((ar + mt * 16) * ASTRIDE + ko + ak) * 2));
                #pragma unroll
                for (int p = 0; p < 2; ++p) {
                    ldsm4(bf[nxt][p], Bb + (u32)(((bc + p * 16) * ASTRIDE + ko + bk) * 2));
                    ldsm4(bg[nxt][p], Bb + (u32)(((bc + (p + 2) * 16) * ASTRIDE + ko + bk) * 2));
                }
            }
            #pragma unroll
            for (int mt = 0; mt < 2; ++mt) {
                #pragma unroll
                for (int p = 0; p < 2; ++p) {
                    mma16816(acc[mt][2 * p    ], af[cur][mt], bf[cur][p][0], bf[cur][p][1]);
                    mma16816(acc[mt][2 * p + 1], af[cur][mt], bf[cur][p][2], bf[cur][p][3]);
                    mma16816(acc[mt][2 * (p + 2)    ], af[cur][mt], bg[cur][p][0], bg[cur][p][1]);
                    mma16816(acc[mt][2 * (p + 2) + 1], af[cur][mt], bg[cur][p][2], bg[cur][p][3]);
                }
            }
        }

        // ---- barrier-free epilogue ----
        float cnv[16];
        #pragma unroll
        for (int j = 0; j < 8; ++j) {
            int cd = nt * 128 + warp_n * 64 + j * 8 + tig * 2;
            cnv[j * 2]     = cn_s[cd];
            cnv[j * 2 + 1] = cn_s[cd + 1];
        }
        #pragma unroll
        for (int mt = 0; mt < 2; ++mt)
            #pragma unroll
            for (int j = 0; j < 8; ++j)
                #pragma unroll
                for (int c = 0; c < 2; ++c) {
                    float g0 = cnv[j * 2 + c] + acc[mt][j][c];
                    float g1 = cnv[j * 2 + c] + acc[mt][j][2 + c];
                    rm[mt * 2]     = fminf(rm[mt * 2], g0);
                    rm[mt * 2 + 1] = fminf(rm[mt * 2 + 1], g1);
                }
        #pragma unroll
        for (int r4 = 0; r4 < 4; ++r4) {
            rm[r4] = fminf(rm[r4], __shfl_xor_sync(0xFFFFFFFF, rm[r4], 1));
            rm[r4] = fminf(rm[r4], __shfl_xor_sync(0xFFFFFFFF, rm[r4], 2));
        }
        if (tig == 0) {
            #pragma unroll
            for (int r4 = 0; r4 < 4; ++r4)
                atomicMin(&rmin_s[rowv[r4]], f2ord(rm[r4]));
        }
        float thr[4];
        #pragma unroll
        for (int r4 = 0; r4 < 4; ++r4)
            thr[r4] = fminf(rm[r4], ord2f(rmin_s[rowv[r4]])) + marg_s[rowv[r4]];

        #pragma unroll
        for (int mt = 0; mt < 2; ++mt)
            #pragma unroll
            for (int j = 0; j < 8; ++j)
                #pragma unroll
                for (int c = 0; c < 2; ++c) {
                    int code = nt * 128 + warp_n * 64 + j * 8 + tig * 2 + c;
                    float g0 = cnv[j * 2 + c] + acc[mt][j][c];
                    float g1 = cnv[j * 2 + c] + acc[mt][j][2 + c];
                    if (g0 <= thr[mt * 2]) {
                        int row = warp_m * 32 + mt * 16 + gid;
                        int sl = atomicAdd(&cnt_s[row], 1);
                        if (sl < CAP) cand_s[row * CAP + sl] = (u16)code;
                    }
                    if (g1 <= thr[mt * 2 + 1]) {
                        int row = warp_m * 32 + mt * 16 + 8 + gid;
                        int sl = atomicAdd(&cnt_s[row], 1);
                        if (sl < CAP) cand_s[row * CAP + sl] = (u16)code;
                    }
                }
    }
    __syncthreads();

    if (t < 128) {
        int c = cnt_s[t];
        g_ccnt[n0 + t] = (c > CAP) ? 255 : (unsigned char)c;
    }
    for (int i = t; i < 128 * CAP; i += 256)
        g_cand[(size_t)n0 * CAP + i] = cand_s[i];
}

// ---------------------------------------------------------------------------
// k2: fused finish = exact verify (candidate-parallel) + gather/STE + loss +
// last-block loss write. (validated R12 form)
// ---------------------------------------------------------------------------
__global__ void __launch_bounds__(256)
finish_kernel(const float* __restrict__ z, const float* __restrict__ cb,
              float* __restrict__ out) {
    __shared__ float q_s[32][257];
    __shared__ int   win_s[32];
    __shared__ float rs[256];

    const int t   = threadIdx.x;
    const int n0  = blockIdx.x * 32;
    const int b   = n0 >> 10;
    const int hw0 = n0 & 1023;

    // ---- phase 1: exact argmin per row ----
    {
        const int r    = t >> 3;        // row 0..31
        const int slot = t & 7;
        const int n    = n0 + r;
        const int cnt  = g_ccnt[n];
        u64 key = ~0ull;
        if (cnt == 1) {
            if (slot == 0) key = skey(-3.4e38f, g_cand[(size_t)n * CAP] & 1023);
        } else {
            const float* zb = z + (size_t)b * (D * 1024) + hw0 + r;
            float zn = g_znorm[n];
            int lim   = (cnt <= CAP) ? cnt : Kc;
            for (int i = slot; i < lim; i += 8) {
                int code = (cnt <= CAP) ? (g_cand[(size_t)n * CAP + i] & 1023) : i;
                const float* cr = cb + (size_t)code * D;
                float dot = 0.0f;
                #pragma unroll 8
                for (int d = 0; d < D; ++d)
                    dot = fmaf(zb[(size_t)d * 1024], cr[d], dot);
                float t1 = __fadd_rn(zn, g_cnorm[code]);
                float sc = __fadd_rn(t1, __fmul_rn(-2.0f, dot));
                u64 k = skey(sc, code);
                if (k < key) key = k;
            }
        }
        #pragma unroll
        for (int o = 4; o > 0; o >>= 1) {
            u32 hi = (u32)(key >> 32), lo = (u32)key;
            u32 ohi = __shfl_xor_sync(0xFFFFFFFF, hi, o, 8);
            u32 olo = __shfl_xor_sync(0xFFFFFFFF, lo, o, 8);
            u64 ok = ((u64)ohi << 32) | olo;
            if (ok < key) key = ok;
        }
        if (slot == 0) {
            int bi = (int)(key & 1023u);
            win_s[r] = bi;
            out[Z_ELEMS + n] = (float)bi;
        }
    }
    __syncthreads();

    // ---- phase 2: gather + STE + loss ----
    for (int i = t; i < 32 * 256; i += 256) {
        int j = i >> 8, d = i & 255;
        q_s[j][d] = cb[(size_t)win_s[j] * D + d];
    }
    __syncthreads();

    const float* zb = z   + (size_t)b * (D * 1024) + hw0;
    float*       ob = out + (size_t)b * (D * 1024) + hw0;
    float ls = 0.0f;
    #pragma unroll
    for (int it = 0; it < 8; ++it) {
        int idx = t + it * 256;
        int j4  = (idx & 7) * 4;
        int d   = idx >> 3;
        float4 zv = *(const float4*)&zb[(size_t)d * 1024 + j4];
        float4 qv;
        qv.x = q_s[j4    ][d];
        qv.y = q_s[j4 + 1][d];
        qv.z = q_s[j4 + 2][d];
        qv.w = q_s[j4 + 3][d];
        float4 ov;
        float dx = __fadd_rn(qv.x, -zv.x); ov.x = __fadd_rn(zv.x, dx);
        float dy = __fadd_rn(qv.y, -zv.y); ov.y = __fadd_rn(zv.y, dy);
        float dz = __fadd_rn(qv.z, -zv.z); ov.z = __fadd_rn(zv.z, dz);
        float dw = __fadd_rn(qv.w, -zv.w); ov.w = __fadd_rn(zv.w, dw);
        *(float4*)&ob[(size_t)d * 1024 + j4] = ov;
        ls += dx * dx + dy * dy + dz * dz + dw * dw;
    }
    rs[t] = ls;
    __syncthreads();
    #pragma unroll
    for (int s = 128; s > 0; s >>= 1) {
        if (t < s) rs[t] += rs[t + s];
        __syncthreads();
    }
    if (t == 0) {
        atomicAdd(&g_loss, rs[0]);
        __threadfence();
        unsigned tick = atomicAdd(&g_done, 1u);
        if (tick == (NROWS / 32) - 1) {            // last block finalizes
            out[Z_ELEMS + NROWS] = 1.25f * g_loss / (float)Z_ELEMS;
            g_loss = 0.0f;                          // reset for next replay
            g_done = 0u;
        }
    }
}

// ---------------------------------------------------------------------------
extern "C" void kernel_launch(void* const* d_in, const int* in_sizes, int n_in,
                              void* d_out, int out_size) {
    const float* z  = (const float*)d_in[0];
    const float* cb = (const float*)d_in[1];
    float* out = (float*)d_out;

    const int mma_smem = 3 * TILE_B + 4096 + 128 * 4 * 3 + 128 * CAP * 2; // 216576

    cudaFuncSetAttribute(mma_cand_kernel,
                         cudaFuncAttributeMaxDynamicSharedMemorySize, mma_smem);

    prep_kernel<<<128, 128>>>(cb);
    mma_cand_kernel<<<NROWS / 128, 256, mma_smem>>>(z);
    finish_kernel<<<NROWS / 32, 256>>>(z, cb, out);
}

// round 14
// speedup vs baseline: 1.1699x; 1.1699x over previous
#include <cuda_runtime.h>
#include <cuda_bf16.h>
#include <cstdint>

#define D       256
#define Kc      1024
#define NROWS   32768
#define Z_ELEMS 8388608
#define CAP     32
#define ASTRIDE 264          // bf16 row stride in smem (256 + 8 pad -> 528B rows)
#define TILE_B  67584        // 128 rows * 528 B

typedef unsigned int u32;
typedef unsigned long long u64;
typedef unsigned short u16;

// ---------------- device globals (no cudaMalloc allowed) -------------------
__device__ float g_cnorm[Kc];
__device__ int   g_cnmax;                // ordered-int max of cnorm (atomicMax, idempotent)
__device__ float g_znorm[NROWS];
__device__ float g_loss;
__device__ unsigned g_done;
__device__ uint4 g_cbbf4[Kc * 32];       // bf16(cb), [k][256] row-major (512B/row)
__device__ u16   g_cand[NROWS * CAP];
__device__ unsigned char g_ccnt[NROWS];

// ---------------- helpers --------------------------------------------------
__device__ __forceinline__ u32 smem_u32(const void* p) {
    u32 a; asm("{ .reg .u64 t; cvta.to.shared.u64 t, %1; cvt.u32.u64 %0, t; }" : "=r"(a) : "l"(p));
    return a;
}
__device__ __forceinline__ void ldsm4(u32* r, u32 addr) {
    asm volatile("ldmatrix.sync.aligned.m8n8.x4.shared.b16 {%0,%1,%2,%3}, [%4];"
        : "=r"(r[0]), "=r"(r[1]), "=r"(r[2]), "=r"(r[3]) : "r"(addr));
}
__device__ __forceinline__ void mma16816(float* c, const u32* a, u32 b0, u32 b1) {
    asm volatile("mma.sync.aligned.m16n8k16.row.col.f32.bf16.bf16.f32 "
        "{%0,%1,%2,%3}, {%4,%5,%6,%7}, {%8,%9}, {%0,%1,%2,%3};"
        : "+f"(c[0]), "+f"(c[1]), "+f"(c[2]), "+f"(c[3])
        : "r"(a[0]), "r"(a[1]), "r"(a[2]), "r"(a[3]), "r"(b0), "r"(b1));
}
__device__ __forceinline__ void cpasync16(u32 dst, const void* src) {
    asm volatile("cp.async.cg.shared.global [%0], [%1], 16;" :: "r"(dst), "l"(src));
}
__device__ __forceinline__ void cpcommit() {
    asm volatile("cp.async.commit_group;" ::: "memory");
}
__device__ __forceinline__ void cpwait0() {
    asm volatile("cp.async.wait_group 0;" ::: "memory");
}
__device__ __forceinline__ int f2ord(float f) {
    int i = __float_as_int(f);
    return i >= 0 ? i : i ^ 0x7FFFFFFF;
}
__device__ __forceinline__ float ord2f(int i) {
    return __int_as_float(i >= 0 ? i : i ^ 0x7FFFFFFF);
}
// unsigned monotone key for lexicographic (score, code) minimum
__device__ __forceinline__ u64 skey(float sc, int code) {
    u32 o = (u32)f2ord(sc) ^ 0x80000000u;
    return ((u64)o << 32) | (u32)code;
}

// ---------------------------------------------------------------------------
// k0: warp-per-code prep (validated 6.8us). Coalesced row load + bf16 convert;
// lane 0 runs the bit-exact sequential unfused norm chain. Block max ->
// atomicMax into g_cnmax (positive values, idempotent across graph replays).
// ---------------------------------------------------------------------------
__global__ void __launch_bounds__(128)
prep_kernel(const float* __restrict__ cb) {
    __shared__ float stage[4][264];
    __shared__ float nrm[4];
    const int t    = threadIdx.x;
    const int lane = t & 31;
    const int w    = t >> 5;
    #pragma unroll
    for (int pass = 0; pass < 2; ++pass) {
        int c = blockIdx.x * 8 + pass * 4 + w;
        const float* row = cb + (size_t)c * D;
        float4 v0[2];
        u16 pk[8];
        #pragma unroll
        for (int h = 0; h < 2; ++h) {
            v0[h] = *(const float4*)&row[lane * 8 + h * 4];
            __nv_bfloat16 b0 = __float2bfloat16(v0[h].x);
            __nv_bfloat16 b1 = __float2bfloat16(v0[h].y);
            __nv_bfloat16 b2 = __float2bfloat16(v0[h].z);
            __nv_bfloat16 b3 = __float2bfloat16(v0[h].w);
            pk[h * 4 + 0] = *(u16*)&b0; pk[h * 4 + 1] = *(u16*)&b1;
            pk[h * 4 + 2] = *(u16*)&b2; pk[h * 4 + 3] = *(u16*)&b3;
            *(float4*)&stage[w][lane * 8 + h * 4] = v0[h];
        }
        g_cbbf4[(size_t)c * 32 + lane] = *(uint4*)pk;
        __syncwarp();
        if (lane == 0) {
            float s = 0.0f;
            #pragma unroll 8
            for (int d = 0; d < D; ++d) {
                float v = stage[w][d];
                s = __fadd_rn(s, __fmul_rn(v, v));   // sequential ascending d, unfused
            }
            g_cnorm[c] = s;
            nrm[w] = (pass == 0) ? s : fmaxf(nrm[w], s);
        }
        __syncwarp();
    }
    __syncthreads();
    if (t == 0)
        atomicMax(&g_cnmax, f2ord(fmaxf(fmaxf(nrm[0], nrm[1]), fmaxf(nrm[2], nrm[3]))));
}

// ---------------------------------------------------------------------------
// k1: mma.sync bf16 GEMM + candidate filter (validated R12 form: 8 warps,
// cp.async double-buffered B, register-double-buffered k-loop, barrier-free
// conservative filter -> superset of exact argmin + quantized ties).
// ---------------------------------------------------------------------------
__global__ void __launch_bounds__(256, 1)
mma_cand_kernel(const float* __restrict__ z) {
    extern __shared__ char smr[];
    u16*   Asm    = (u16*)smr;                         // [128][264]
    float* cn_s   = (float*)(smr + 3 * TILE_B);        // [1024]
    float* marg_s = cn_s + 1024;                       // [128]
    int*   rmin_s = (int*)(marg_s + 128);              // [128]
    int*   cnt_s  = rmin_s + 128;                      // [128]
    u16*   cand_s = (u16*)(cnt_s + 128);               // [128][CAP]

    const int t      = threadIdx.x;
    const int lane   = t & 31;
    const int wid    = t >> 5;
    const int warp_m = wid & 3;
    const int warp_n = wid >> 2;
    const int gid    = lane >> 2;
    const int tig    = lane & 3;
    const int n0     = blockIdx.x * 128;

    const u32 Abase = smem_u32(Asm);
    const u32 Bbase = Abase + TILE_B;

    {   // prefetch B tile 0
        const char* src = ((const char*)g_cbbf4);
        for (int i = t; i < 4096; i += 256) {
            int r = i >> 5, c = i & 31;
            cpasync16(Bbase + (u32)(r * 528 + c * 16), src + r * 512 + c * 16);
        }
        cpcommit();
    }

    // ---- prologue: A conversion + exact znorm (threads<128); cn (others) ----
    if (t < 128) {
        const int b  = n0 >> 10;
        const int hw = (n0 & 1023) + t;
        const float* zb = z + (size_t)b * (D * 1024) + hw;
        float s = 0.0f;
        for (int d0 = 0; d0 < D; d0 += 8) {
            u16 pk[8];
            #pragma unroll
            for (int i = 0; i < 8; ++i) {
                float v = zb[(size_t)(d0 + i) * 1024];
                s = __fadd_rn(s, __fmul_rn(v, v));      // exact sequential ascending d
                __nv_bfloat16 h = __float2bfloat16(-2.0f * v);
                pk[i] = *(u16*)&h;
            }
            *(uint4*)&Asm[t * ASTRIDE + d0] = *(uint4*)pk;
        }
        g_znorm[n0 + t] = s;
        float cm = ord2f(g_cnmax);
        marg_s[t] = 0.015625f * sqrtf(s * cm) + 3e-4f;
        rmin_s[t] = 0x7F800000;
        cnt_s[t]  = 0;
    } else {
        for (int i = t - 128; i < Kc; i += 128) cn_s[i] = g_cnorm[i];
    }

    float rm[4] = {3.4e38f, 3.4e38f, 3.4e38f, 3.4e38f};
    int   rowv[4];
    #pragma unroll
    for (int r4 = 0; r4 < 4; ++r4)
        rowv[r4] = warp_m * 32 + (r4 >> 1) * 16 + (r4 & 1) * 8 + gid;

    const int ar = warp_m * 32 + (lane & 15);
    const int ak = (lane >> 4) << 3;
    const int bc = warp_n * 64 + ((lane >> 4) & 1) * 8 + (lane & 7);
    const int bk = ((lane >> 3) & 1) * 8;

    for (int nt = 0; nt < 8; ++nt) {
        cpwait0();
        __syncthreads();
        if (nt < 7) {
            const char* src = ((const char*)g_cbbf4) + (size_t)(nt + 1) * 128 * 512;
            u32 dstb = Bbase + (u32)(((nt + 1) & 1) * TILE_B);
            for (int i = t; i < 4096; i += 256) {
                int r = i >> 5, c = i & 31;
                cpasync16(dstb + (u32)(r * 528 + c * 16), src + r * 512 + c * 16);
            }
            cpcommit();
        }
        const u32 Bb = Bbase + (u32)((nt & 1) * TILE_B);

        float acc[2][8][4];
        #pragma unroll
        for (int mt = 0; mt < 2; ++mt)
            #pragma unroll
            for (int j = 0; j < 8; ++j)
                #pragma unroll
                for (int c = 0; c < 4; ++c) acc[mt][j][c] = 0.0f;

        u32 af[2][2][4], bf[2][2][4], bg[2][2][4];
        #pragma unroll
        for (int mt = 0; mt < 2; ++mt)
            ldsm4(af[0][mt], Abase + (u32)(((ar + mt * 16) * ASTRIDE + ak) * 2));
        #pragma unroll
        for (int p = 0; p < 2; ++p) {
            ldsm4(bf[0][p], Bb + (u32)(((bc + p * 16) * ASTRIDE + bk) * 2));
            ldsm4(bg[0][p], Bb + (u32)(((bc + (p + 2) * 16) * ASTRIDE + bk) * 2));
        }
        #pragma unroll
        for (int kk = 0; kk < 16; ++kk) {
            const int cur = kk & 1, nxt = cur ^ 1;
            if (kk < 15) {
                int ko = (kk + 1) * 16;
                #pragma unroll
                for (int mt = 0; mt < 2; ++mt)
                    ldsm4(af[nxt][mt], Abase + (u32)(((ar + mt * 16) * ASTRIDE + ko + ak) * 2));
                #pragma unroll
                for (int p = 0; p < 2; ++p) {
                    ldsm4(bf[nxt][p], Bb + (u32)(((bc + p * 16) * ASTRIDE + ko + bk) * 2));
                    ldsm4(bg[nxt][p], Bb + (u32)(((bc + (p + 2) * 16) * ASTRIDE + ko + bk) * 2));
                }
            }
            #pragma unroll
            for (int mt = 0; mt < 2; ++mt) {
                #pragma unroll
                for (int p = 0; p < 2; ++p) {
                    mma16816(acc[mt][2 * p    ], af[cur][mt], bf[cur][p][0], bf[cur][p][1]);
                    mma16816(acc[mt][2 * p + 1], af[cur][mt], bf[cur][p][2], bf[cur][p][3]);
                    mma16816(acc[mt][2 * (p + 2)    ], af[cur][mt], bg[cur][p][0], bg[cur][p][1]);
                    mma16816(acc[mt][2 * (p + 2) + 1], af[cur][mt], bg[cur][p][2], bg[cur][p][3]);
                }
            }
        }

        // ---- barrier-free epilogue ----
        float cnv[16];
        #pragma unroll
        for (int j = 0; j < 8; ++j) {
            int cd = nt * 128 + warp_n * 64 + j * 8 + tig * 2;
            cnv[j * 2]     = cn_s[cd];
            cnv[j * 2 + 1] = cn_s[cd + 1];
        }
        #pragma unroll
        for (int mt = 0; mt < 2; ++mt)
            #pragma unroll
            for (int j = 0; j < 8; ++j)
                #pragma unroll
                for (int c = 0; c < 2; ++c) {
                    float g0 = cnv[j * 2 + c] + acc[mt][j][c];
                    float g1 = cnv[j * 2 + c] + acc[mt][j][2 + c];
                    rm[mt * 2]     = fminf(rm[mt * 2], g0);
                    rm[mt * 2 + 1] = fminf(rm[mt * 2 + 1], g1);
                }
        #pragma unroll
        for (int r4 = 0; r4 < 4; ++r4) {
            rm[r4] = fminf(rm[r4], __shfl_xor_sync(0xFFFFFFFF, rm[r4], 1));
            rm[r4] = fminf(rm[r4], __shfl_xor_sync(0xFFFFFFFF, rm[r4], 2));
        }
        if (tig == 0) {
            #pragma unroll
            for (int r4 = 0; r4 < 4; ++r4)
                atomicMin(&rmin_s[rowv[r4]], f2ord(rm[r4]));
        }
        float thr[4];
        #pragma unroll
        for (int r4 = 0; r4 < 4; ++r4)
            thr[r4] = fminf(rm[r4], ord2f(rmin_s[rowv[r4]])) + marg_s[rowv[r4]];

        #pragma unroll
        for (int mt = 0; mt < 2; ++mt)
            #pragma unroll
            for (int j = 0; j < 8; ++j)
                #pragma unroll
                for (int c = 0; c < 2; ++c) {
                    int code = nt * 128 + warp_n * 64 + j * 8 + tig * 2 + c;
                    float g0 = cnv[j * 2 + c] + acc[mt][j][c];
                    float g1 = cnv[j * 2 + c] + acc[mt][j][2 + c];
                    if (g0 <= thr[mt * 2]) {
                        int row = warp_m * 32 + mt * 16 + gid;
                        int sl = atomicAdd(&cnt_s[row], 1);
                        if (sl < CAP) cand_s[row * CAP + sl] = (u16)code;
                    }
                    if (g1 <= thr[mt * 2 + 1]) {
                        int row = warp_m * 32 + mt * 16 + 8 + gid;
                        int sl = atomicAdd(&cnt_s[row], 1);
                        if (sl < CAP) cand_s[row * CAP + sl] = (u16)code;
                    }
                }
    }
    __syncthreads();

    if (t < 128) {
        int c = cnt_s[t];
        g_ccnt[n0 + t] = (c > CAP) ? 255 : (unsigned char)c;
    }
    for (int i = t; i < 128 * CAP; i += 256)
        g_cand[(size_t)n0 * CAP + i] = cand_s[i];
}

// ---------------------------------------------------------------------------
// k2: fused finish. z tile staged in smem ONCE (coalesced); exact verify reads
// z from smem + float4 codebook loads (same sequential ascending-d fmaf order
// -> bit-exact); gather/STE/loss reuse the staged z (no second gmem z read).
// ---------------------------------------------------------------------------
__global__ void __launch_bounds__(256)
finish_kernel(const float* __restrict__ z, const float* __restrict__ cb,
              float* __restrict__ out) {
    __shared__ float z_s[32][257];
    __shared__ float q_s[32][257];
    __shared__ int   win_s[32];
    __shared__ float rs[256];

    const int t   = threadIdx.x;
    const int n0  = blockIdx.x * 32;
    const int b   = n0 >> 10;
    const int hw0 = n0 & 1023;
    const float* zb = z + (size_t)b * (D * 1024) + hw0;

    // ---- stage z tile: coalesced gmem reads, conflict-free smem writes ----
    for (int i = t; i < 32 * 256; i += 256) {
        int d = i >> 5, j = i & 31;                 // consecutive t -> consecutive j
        z_s[j][d] = zb[(size_t)d * 1024 + j];
    }
    __syncthreads();

    // ---- phase 1: exact argmin per row (8 threads/row) ----
    {
        const int r    = t >> 3;
        const int slot = t & 7;
        const int n    = n0 + r;
        const int cnt  = g_ccnt[n];
        u64 key = ~0ull;
        if (cnt == 1) {
            if (slot == 0) key = skey(-3.4e38f, g_cand[(size_t)n * CAP] & 1023);
        } else {
            float zn = g_znorm[n];
            int lim  = (cnt <= CAP) ? cnt : Kc;
            for (int i = slot; i < lim; i += 8) {
                int code = (cnt <= CAP) ? (g_cand[(size_t)n * CAP + i] & 1023) : i;
                const float4* cr4 = (const float4*)(cb + (size_t)code * D);
                float dot = 0.0f;
                #pragma unroll 4
                for (int d4 = 0; d4 < D / 4; ++d4) {
                    float4 c4 = cr4[d4];
                    int d = d4 * 4;
                    dot = fmaf(z_s[r][d    ], c4.x, dot);   // sequential ascending d
                    dot = fmaf(z_s[r][d + 1], c4.y, dot);
                    dot = fmaf(z_s[r][d + 2], c4.z, dot);
                    dot = fmaf(z_s[r][d + 3], c4.w, dot);
                }
                float t1 = __fadd_rn(zn, g_cnorm[code]);
                float sc = __fadd_rn(t1, __fmul_rn(-2.0f, dot));
                u64 k = skey(sc, code);
                if (k < key) key = k;
            }
        }
        #pragma unroll
        for (int o = 4; o > 0; o >>= 1) {
            u32 hi = (u32)(key >> 32), lo = (u32)key;
            u32 ohi = __shfl_xor_sync(0xFFFFFFFF, hi, o, 8);
            u32 olo = __shfl_xor_sync(0xFFFFFFFF, lo, o, 8);
            u64 ok = ((u64)ohi << 32) | olo;
            if (ok < key) key = ok;
        }
        if (slot == 0) {
            int bi = (int)(key & 1023u);
            win_s[r] = bi;
            out[Z_ELEMS + n] = (float)bi;
        }
    }
    __syncthreads();

    // ---- phase 2: gather + STE + loss (z from smem, out coalesced) ----
    for (int i = t; i < 32 * 256; i += 256) {
        int j = i >> 8, d = i & 255;
        q_s[j][d] = cb[(size_t)win_s[j] * D + d];
    }
    __syncthreads();

    float*       ob = out + (size_t)b * (D * 1024) + hw0;
    float ls = 0.0f;
    #pragma unroll
    for (int it = 0; it < 8; ++it) {
        int idx = t + it * 256;
        int j4  = (idx & 7) * 4;
        int d   = idx >> 3;
        float4 zv;
        zv.x = z_s[j4    ][d];
        zv.y = z_s[j4 + 1][d];
        zv.z = z_s[j4 + 2][d];
        zv.w = z_s[j4 + 3][d];
        float4 qv;
        qv.x = q_s[j4    ][d];
        qv.y = q_s[j4 + 1][d];
        qv.z = q_s[j4 + 2][d];
        qv.w = q_s[j4 + 3][d];
        float4 ov;
        float dx = __fadd_rn(qv.x, -zv.x); ov.x = __fadd_rn(zv.x, dx);
        float dy = __fadd_rn(qv.y, -zv.y); ov.y = __fadd_rn(zv.y, dy);
        float dz = __fadd_rn(qv.z, -zv.z); ov.z = __fadd_rn(zv.z, dz);
        float dw = __fadd_rn(qv.w, -zv.w); ov.w = __fadd_rn(zv.w, dw);
        *(float4*)&ob[(size_t)d * 1024 + j4] = ov;
        ls += dx * dx + dy * dy + dz * dz + dw * dw;
    }
    rs[t] = ls;
    __syncthreads();
    #pragma unroll
    for (int s = 128; s > 0; s >>= 1) {
        if (t < s) rs[t] += rs[t + s];
        __syncthreads();
    }
    if (t == 0) {
        atomicAdd(&g_loss, rs[0]);
        __threadfence();
        unsigned tick = atomicAdd(&g_done, 1u);
        if (tick == (NROWS / 32) - 1) {
            out[Z_ELEMS + NROWS] = 1.25f * g_loss / (float)Z_ELEMS;
            g_loss = 0.0f;
            g_done = 0u;
        }
    }
}

// ---------------------------------------------------------------------------
extern "C" void kernel_launch(void* const* d_in, const int* in_sizes, int n_in,
                              void* d_out, int out_size) {
    const float* z  = (const float*)d_in[0];
    const float* cb = (const float*)d_in[1];
    float* out = (float*)d_out;

    const int mma_smem = 3 * TILE_B + 4096 + 128 * 4 * 3 + 128 * CAP * 2; // 216576

    cudaFuncSetAttribute(mma_cand_kernel,
                         cudaFuncAttributeMaxDynamicSharedMemorySize, mma_smem);

    prep_kernel<<<128, 128>>>(cb);
    mma_cand_kernel<<<NROWS / 128, 256, mma_smem>>>(z);
    finish_kernel<<<NROWS / 32, 256>>>(z, cb, out);
}

// round 15
// speedup vs baseline: 1.4777x; 1.2631x over previous
#include <cuda_runtime.h>
#include <cuda_bf16.h>
#include <cstdint>

#define D       256
#define Kc      1024
#define NROWS   32768
#define Z_ELEMS 8388608
#define CAP     32
#define ASTRIDE 264          // bf16 row stride in smem (256 + 8 pad -> 528B rows)
#define RTILE   64           // rows per CTA
#define BTILE   64           // codes per B tile
#define NTILES  (Kc / BTILE) // 16
#define TILE_A  (RTILE * 528)   // 33792
#define TILE_Bb (BTILE * 528)   // 33792

typedef unsigned int u32;
typedef unsigned long long u64;
typedef unsigned short u16;

// ---------------- device globals (no cudaMalloc allowed) -------------------
__device__ float g_cnorm[Kc];
__device__ int   g_cnmax;                // ordered-int max of cnorm (atomicMax, idempotent)
__device__ float g_znorm[NROWS];
__device__ float g_loss;
__device__ unsigned g_done;
__device__ uint4 g_cbbf4[Kc * 32];       // bf16(cb), [k][256] row-major (512B/row)
__device__ u16   g_cand[NROWS * CAP];
__device__ unsigned char g_ccnt[NROWS];

// ---------------- helpers --------------------------------------------------
__device__ __forceinline__ u32 smem_u32(const void* p) {
    u32 a; asm("{ .reg .u64 t; cvta.to.shared.u64 t, %1; cvt.u32.u64 %0, t; }" : "=r"(a) : "l"(p));
    return a;
}
__device__ __forceinline__ void ldsm4(u32* r, u32 addr) {
    asm volatile("ldmatrix.sync.aligned.m8n8.x4.shared.b16 {%0,%1,%2,%3}, [%4];"
        : "=r"(r[0]), "=r"(r[1]), "=r"(r[2]), "=r"(r[3]) : "r"(addr));
}
__device__ __forceinline__ void mma16816(float* c, const u32* a, u32 b0, u32 b1) {
    asm volatile("mma.sync.aligned.m16n8k16.row.col.f32.bf16.bf16.f32 "
        "{%0,%1,%2,%3}, {%4,%5,%6,%7}, {%8,%9}, {%0,%1,%2,%3};"
        : "+f"(c[0]), "+f"(c[1]), "+f"(c[2]), "+f"(c[3])
        : "r"(a[0]), "r"(a[1]), "r"(a[2]), "r"(a[3]), "r"(b0), "r"(b1));
}
__device__ __forceinline__ void cpasync16(u32 dst, const void* src) {
    asm volatile("cp.async.cg.shared.global [%0], [%1], 16;" :: "r"(dst), "l"(src));
}
__device__ __forceinline__ void cpcommit() {
    asm volatile("cp.async.commit_group;" ::: "memory");
}
__device__ __forceinline__ void cpwait0() {
    asm volatile("cp.async.wait_group 0;" ::: "memory");
}
__device__ __forceinline__ int f2ord(float f) {
    int i = __float_as_int(f);
    return i >= 0 ? i : i ^ 0x7FFFFFFF;
}
__device__ __forceinline__ float ord2f(int i) {
    return __int_as_float(i >= 0 ? i : i ^ 0x7FFFFFFF);
}
// unsigned monotone key for lexicographic (score, code) minimum
__device__ __forceinline__ u64 skey(float sc, int code) {
    u32 o = (u32)f2ord(sc) ^ 0x80000000u;
    return ((u64)o << 32) | (u32)code;
}

// ---------------------------------------------------------------------------
// k0: warp-per-code prep (validated ~7-9us). Coalesced row load + bf16
// convert; lane 0 runs the bit-exact sequential unfused norm chain.
// ---------------------------------------------------------------------------
__global__ void __launch_bounds__(128)
prep_kernel(const float* __restrict__ cb) {
    __shared__ float stage[4][264];
    __shared__ float nrm[4];
    const int t    = threadIdx.x;
    const int lane = t & 31;
    const int w    = t >> 5;
    #pragma unroll
    for (int pass = 0; pass < 2; ++pass) {
        int c = blockIdx.x * 8 + pass * 4 + w;
        const float* row = cb + (size_t)c * D;
        float4 v0[2];
        u16 pk[8];
        #pragma unroll
        for (int h = 0; h < 2; ++h) {
            v0[h] = *(const float4*)&row[lane * 8 + h * 4];
            __nv_bfloat16 b0 = __float2bfloat16(v0[h].x);
            __nv_bfloat16 b1 = __float2bfloat16(v0[h].y);
            __nv_bfloat16 b2 = __float2bfloat16(v0[h].z);
            __nv_bfloat16 b3 = __float2bfloat16(v0[h].w);
            pk[h * 4 + 0] = *(u16*)&b0; pk[h * 4 + 1] = *(u16*)&b1;
            pk[h * 4 + 2] = *(u16*)&b2; pk[h * 4 + 3] = *(u16*)&b3;
            *(float4*)&stage[w][lane * 8 + h * 4] = v0[h];
        }
        g_cbbf4[(size_t)c * 32 + lane] = *(uint4*)pk;
        __syncwarp();
        if (lane == 0) {
            float s = 0.0f;
            #pragma unroll 8
            for (int d = 0; d < D; ++d) {
                float v = stage[w][d];
                s = __fadd_rn(s, __fmul_rn(v, v));   // sequential ascending d, unfused
            }
            g_cnorm[c] = s;
            nrm[w] = (pass == 0) ? s : fmaxf(nrm[w], s);
        }
        __syncwarp();
    }
    __syncthreads();
    if (t == 0)
        atomicMax(&g_cnmax, f2ord(fmaxf(fmaxf(nrm[0], nrm[1]), fmaxf(nrm[2], nrm[3]))));
}

// ---------------------------------------------------------------------------
// k1: mma.sync bf16 GEMM + candidate filter. 64-ROW CTA / 64-CODE B TILES:
// smem ~108 KB -> 2 CTAs/SM (16 warps/SM), doubling latency hiding for the
// ldsm->mma chains. 8 warps: warp_m = wid&1 (32 rows), warp_n = wid>>1
// (16 codes). Register double-buffered k-loop; barrier-free conservative
// filter (superset of exact argmin + quantized ties).
// ---------------------------------------------------------------------------
__global__ void __launch_bounds__(256, 2)
mma_cand_kernel(const float* __restrict__ z) {
    extern __shared__ char smr[];
    u16*   Asm    = (u16*)smr;                           // [64][264]
    // B stages at TILE_A, TILE_A + TILE_Bb
    float* cn_s   = (float*)(smr + TILE_A + 2 * TILE_Bb); // [1024]
    float* marg_s = cn_s + 1024;                          // [64]
    int*   rmin_s = (int*)(marg_s + 64);                  // [64]
    int*   cnt_s  = rmin_s + 64;                          // [64]
    u16*   cand_s = (u16*)(cnt_s + 64);                   // [64][CAP]

    const int t      = threadIdx.x;
    const int lane   = t & 31;
    const int wid    = t >> 5;
    const int warp_m = wid & 1;     // 32-row group
    const int warp_n = wid >> 1;    // 16-code group
    const int gid    = lane >> 2;
    const int tig    = lane & 3;
    const int n0     = blockIdx.x * RTILE;

    const u32 Abase = smem_u32(Asm);
    const u32 Bbase = Abase + TILE_A;

    {   // prefetch B tile 0 (64 codes x 512B)
        const char* src = ((const char*)g_cbbf4);
        for (int i = t; i < 2048; i += 256) {
            int r = i >> 5, c = i & 31;
            cpasync16(Bbase + (u32)(r * 528 + c * 16), src + r * 512 + c * 16);
        }
        cpcommit();
    }

    // ---- prologue: A conversion + exact znorm (threads<64); cn (others) ----
    if (t < RTILE) {
        const int b  = n0 >> 10;
        const int hw = (n0 & 1023) + t;
        const float* zb = z + (size_t)b * (D * 1024) + hw;
        float s = 0.0f;
        for (int d0 = 0; d0 < D; d0 += 8) {
            u16 pk[8];
            #pragma unroll
            for (int i = 0; i < 8; ++i) {
                float v = zb[(size_t)(d0 + i) * 1024];
                s = __fadd_rn(s, __fmul_rn(v, v));      // exact sequential ascending d
                __nv_bfloat16 h = __float2bfloat16(-2.0f * v);
                pk[i] = *(u16*)&h;
            }
            *(uint4*)&Asm[t * ASTRIDE + d0] = *(uint4*)pk;
        }
        g_znorm[n0 + t] = s;
        float cm = ord2f(g_cnmax);
        marg_s[t] = 0.015625f * sqrtf(s * cm) + 3e-4f;
        rmin_s[t] = 0x7F800000;
        cnt_s[t]  = 0;
    } else {
        for (int i = t - RTILE; i < Kc; i += 256 - RTILE) cn_s[i] = g_cnorm[i];
    }

    float rm[4] = {3.4e38f, 3.4e38f, 3.4e38f, 3.4e38f};
    int   rowv[4];
    #pragma unroll
    for (int r4 = 0; r4 < 4; ++r4)
        rowv[r4] = warp_m * 32 + (r4 >> 1) * 16 + (r4 & 1) * 8 + gid;

    const int ar = warp_m * 32 + (lane & 15);
    const int ak = (lane >> 4) << 3;
    const int bc = warp_n * 16 + ((lane >> 4) & 1) * 8 + (lane & 7);
    const int bk = ((lane >> 3) & 1) * 8;

    for (int nt = 0; nt < NTILES; ++nt) {
        cpwait0();
        __syncthreads();   // B[nt] visible; prior stage fully consumed
        if (nt < NTILES - 1) {
            const char* src = ((const char*)g_cbbf4) + (size_t)(nt + 1) * BTILE * 512;
            u32 dstb = Bbase + (u32)(((nt + 1) & 1) * TILE_Bb);
            for (int i = t; i < 2048; i += 256) {
                int r = i >> 5, c = i & 31;
                cpasync16(dstb + (u32)(r * 528 + c * 16), src + r * 512 + c * 16);
            }
            cpcommit();
        }
        const u32 Bb = Bbase + (u32)((nt & 1) * TILE_Bb);

        float acc[2][2][4];
        #pragma unroll
        for (int mt = 0; mt < 2; ++mt)
            #pragma unroll
            for (int j = 0; j < 2; ++j)
                #pragma unroll
                for (int c = 0; c < 4; ++c) acc[mt][j][c] = 0.0f;

        // ---- register double-buffered k-loop ----
        u32 af[2][2][4], bq[2][4];
        #pragma unroll
        for (int mt = 0; mt < 2; ++mt)
            ldsm4(af[0][mt], Abase + (u32)(((ar + mt * 16) * ASTRIDE + ak) * 2));
        ldsm4(bq[0], Bb + (u32)((bc * ASTRIDE + bk) * 2));
        #pragma unroll
        for (int kk = 0; kk < 16; ++kk) {
            const int cur = kk & 1, nxt = cur ^ 1;
            if (kk < 15) {
                int ko = (kk + 1) * 16;
                #pragma unroll
                for (int mt = 0; mt < 2; ++mt)
                    ldsm4(af[nxt][mt], Abase + (u32)(((ar + mt * 16) * ASTRIDE + ko + ak) * 2));
                ldsm4(bq[nxt], Bb + (u32)((bc * ASTRIDE + ko + bk) * 2));
            }
            #pragma unroll
            for (int mt = 0; mt < 2; ++mt) {
                mma16816(acc[mt][0], af[cur][mt], bq[cur][0], bq[cur][1]);
                mma16816(acc[mt][1], af[cur][mt], bq[cur][2], bq[cur][3]);
            }
        }

        // ---- barrier-free epilogue ----
        float cnv[4];
        #pragma unroll
        for (int j = 0; j < 2; ++j) {
            int cd = nt * BTILE + warp_n * 16 + j * 8 + tig * 2;
            cnv[j * 2]     = cn_s[cd];
            cnv[j * 2 + 1] = cn_s[cd + 1];
        }
        #pragma unroll
        for (int mt = 0; mt < 2; ++mt)
            #pragma unroll
            for (int j = 0; j < 2; ++j)
                #pragma unroll
                for (int c = 0; c < 2; ++c) {
                    float g0 = cnv[j * 2 + c] + acc[mt][j][c];       // row gid
                    float g1 = cnv[j * 2 + c] + acc[mt][j][2 + c];   // row gid+8
                    rm[mt * 2]     = fminf(rm[mt * 2], g0);
                    rm[mt * 2 + 1] = fminf(rm[mt * 2 + 1], g1);
                }
        #pragma unroll
        for (int r4 = 0; r4 < 4; ++r4) {
            rm[r4] = fminf(rm[r4], __shfl_xor_sync(0xFFFFFFFF, rm[r4], 1));
            rm[r4] = fminf(rm[r4], __shfl_xor_sync(0xFFFFFFFF, rm[r4], 2));
        }
        if (tig == 0) {
            #pragma unroll
            for (int r4 = 0; r4 < 4; ++r4)
                atomicMin(&rmin_s[rowv[r4]], f2ord(rm[r4]));
        }
        float thr[4];
        #pragma unroll
        for (int r4 = 0; r4 < 4; ++r4)
            thr[r4] = fminf(rm[r4], ord2f(rmin_s[rowv[r4]])) + marg_s[rowv[r4]];

        #pragma unroll
        for (int mt = 0; mt < 2; ++mt)
            #pragma unroll
            for (int j = 0; j < 2; ++j)
                #pragma unroll
                for (int c = 0; c < 2; ++c) {
                    int code = nt * BTILE + warp_n * 16 + j * 8 + tig * 2 + c;
                    float g0 = cnv[j * 2 + c] + acc[mt][j][c];
                    float g1 = cnv[j * 2 + c] + acc[mt][j][2 + c];
                    if (g0 <= thr[mt * 2]) {
                        int row = warp_m * 32 + mt * 16 + gid;
                        int sl = atomicAdd(&cnt_s[row], 1);
                        if (sl < CAP) cand_s[row * CAP + sl] = (u16)code;
                    }
                    if (g1 <= thr[mt * 2 + 1]) {
                        int row = warp_m * 32 + mt * 16 + 8 + gid;
                        int sl = atomicAdd(&cnt_s[row], 1);
                        if (sl < CAP) cand_s[row * CAP + sl] = (u16)code;
                    }
                }
    }
    __syncthreads();

    if (t < RTILE) {
        int c = cnt_s[t];
        g_ccnt[n0 + t] = (c > CAP) ? 255 : (unsigned char)c;
    }
    for (int i = t; i < RTILE * CAP; i += 256)
        g_cand[(size_t)n0 * CAP + i] = cand_s[i];
}

// ---------------------------------------------------------------------------
// k2: fused finish (validated R14 form: z staged once, float4 cb loads,
// bit-exact sequential verify, lexicographic (score,code) min).
// ---------------------------------------------------------------------------
__global__ void __launch_bounds__(256)
finish_kernel(const float* __restrict__ z, const float* __restrict__ cb,
              float* __restrict__ out) {
    __shared__ float z_s[32][257];
    __shared__ float q_s[32][257];
    __shared__ int   win_s[32];
    __shared__ float rs[256];

    const int t   = threadIdx.x;
    const int n0  = blockIdx.x * 32;
    const int b   = n0 >> 10;
    const int hw0 = n0 & 1023;
    const float* zb = z + (size_t)b * (D * 1024) + hw0;

    for (int i = t; i < 32 * 256; i += 256) {
        int d = i >> 5, j = i & 31;
        z_s[j][d] = zb[(size_t)d * 1024 + j];
    }
    __syncthreads();

    {
        const int r    = t >> 3;
        const int slot = t & 7;
        const int n    = n0 + r;
        const int cnt  = g_ccnt[n];
        u64 key = ~0ull;
        if (cnt == 1) {
            if (slot == 0) key = skey(-3.4e38f, g_cand[(size_t)n * CAP] & 1023);
        } else {
            float zn = g_znorm[n];
            int lim  = (cnt <= CAP) ? cnt : Kc;
            for (int i = slot; i < lim; i += 8) {
                int code = (cnt <= CAP) ? (g_cand[(size_t)n * CAP + i] & 1023) : i;
                const float4* cr4 = (const float4*)(cb + (size_t)code * D);
                float dot = 0.0f;
                #pragma unroll 4
                for (int d4 = 0; d4 < D / 4; ++d4) {
                    float4 c4 = cr4[d4];
                    int d = d4 * 4;
                    dot = fmaf(z_s[r][d    ], c4.x, dot);
                    dot = fmaf(z_s[r][d + 1], c4.y, dot);
                    dot = fmaf(z_s[r][d + 2], c4.z, dot);
                    dot = fmaf(z_s[r][d + 3], c4.w, dot);
                }
                float t1 = __fadd_rn(zn, g_cnorm[code]);
                float sc = __fadd_rn(t1, __fmul_rn(-2.0f, dot));
                u64 k = skey(sc, code);
                if (k < key) key = k;
            }
        }
        #pragma unroll
        for (int o = 4; o > 0; o >>= 1) {
            u32 hi = (u32)(key >> 32), lo = (u32)key;
            u32 ohi = __shfl_xor_sync(0xFFFFFFFF, hi, o, 8);
            u32 olo = __shfl_xor_sync(0xFFFFFFFF, lo, o, 8);
            u64 ok = ((u64)ohi << 32) | olo;
            if (ok < key) key = ok;
        }
        if (slot == 0) {
            int bi = (int)(key & 1023u);
            win_s[r] = bi;
            out[Z_ELEMS + n] = (float)bi;
        }
    }
    __syncthreads();

    for (int i = t; i < 32 * 256; i += 256) {
        int j = i >> 8, d = i & 255;
        q_s[j][d] = cb[(size_t)win_s[j] * D + d];
    }
    __syncthreads();

    float* ob = out + (size_t)b * (D * 1024) + hw0;
    float ls = 0.0f;
    #pragma unroll
    for (int it = 0; it < 8; ++it) {
        int idx = t + it * 256;
        int j4  = (idx & 7) * 4;
        int d   = idx >> 3;
        float4 zv;
        zv.x = z_s[j4    ][d];
        zv.y = z_s[j4 + 1][d];
        zv.z = z_s[j4 + 2][d];
        zv.w = z_s[j4 + 3][d];
        float4 qv;
        qv.x = q_s[j4    ][d];
        qv.y = q_s[j4 + 1][d];
        qv.z = q_s[j4 + 2][d];
        qv.w = q_s[j4 + 3][d];
        float4 ov;
        float dx = __fadd_rn(qv.x, -zv.x); ov.x = __fadd_rn(zv.x, dx);
        float dy = __fadd_rn(qv.y, -zv.y); ov.y = __fadd_rn(zv.y, dy);
        float dz = __fadd_rn(qv.z, -zv.z); ov.z = __fadd_rn(zv.z, dz);
        float dw = __fadd_rn(qv.w, -zv.w); ov.w = __fadd_rn(zv.w, dw);
        *(float4*)&ob[(size_t)d * 1024 + j4] = ov;
        ls += dx * dx + dy * dy + dz * dz + dw * dw;
    }
    rs[t] = ls;
    __syncthreads();
    #pragma unroll
    for (int s = 128; s > 0; s >>= 1) {
        if (t < s) rs[t] += rs[t + s];
        __syncthreads();
    }
    if (t == 0) {
        atomicAdd(&g_loss, rs[0]);
        __threadfence();
        unsigned tick = atomicAdd(&g_done, 1u);
        if (tick == (NROWS / 32) - 1) {
            out[Z_ELEMS + NROWS] = 1.25f * g_loss / (float)Z_ELEMS;
            g_loss = 0.0f;
            g_done = 0u;
        }
    }
}

// ---------------------------------------------------------------------------
extern "C" void kernel_launch(void* const* d_in, const int* in_sizes, int n_in,
                              void* d_out, int out_size) {
    const float* z  = (const float*)d_in[0];
    const float* cb = (const float*)d_in[1];
    float* out = (float*)d_out;

    const int mma_smem = TILE_A + 2 * TILE_Bb + 4096 + 64 * 4 * 3 + 64 * CAP * 2; // 110336

    cudaFuncSetAttribute(mma_cand_kernel,
                         cudaFuncAttributeMaxDynamicSharedMemorySize, mma_smem);

    prep_kernel<<<128, 128>>>(cb);
    mma_cand_kernel<<<NROWS / RTILE, 256, mma_smem>>>(z);
    finish_kernel<<<NROWS / 32, 256>>>(z, cb, out);
}

// round 16
// speedup vs baseline: 1.6148x; 1.0928x over previous
#include <cuda_runtime.h>
#include <cuda_bf16.h>
#include <cstdint>

#define D       256
#define Kc      1024
#define NROWS   32768
#define Z_ELEMS 8388608
#define CAP     32
#define ASTRIDE 264          // bf16 row stride in smem (256 + 8 pad -> 528B rows)
#define RTILE   64           // rows per CTA (mma)
#define BTILE   64           // codes per B tile
#define NTILES  (Kc / BTILE) // 16
#define TILE_A  (RTILE * 528)   // 33792
#define TILE_Bb (BTILE * 528)   // 33792

typedef unsigned int u32;
typedef unsigned long long u64;
typedef unsigned short u16;

// ---------------- device globals (no cudaMalloc allowed) -------------------
__device__ float g_cnorm[Kc];
__device__ int   g_cnmax;
__device__ float g_znorm[NROWS];
__device__ float g_loss;
__device__ unsigned g_done;
__device__ uint4 g_cbbf4[Kc * 32];       // bf16(cb), [k][256] row-major (512B/row)
__device__ u16   g_cand[NROWS * CAP];
__device__ unsigned char g_ccnt[NROWS];

// ---------------- helpers --------------------------------------------------
__device__ __forceinline__ u32 smem_u32(const void* p) {
    u32 a; asm("{ .reg .u64 t; cvta.to.shared.u64 t, %1; cvt.u32.u64 %0, t; }" : "=r"(a) : "l"(p));
    return a;
}
__device__ __forceinline__ void ldsm4(u32* r, u32 addr) {
    asm volatile("ldmatrix.sync.aligned.m8n8.x4.shared.b16 {%0,%1,%2,%3}, [%4];"
        : "=r"(r[0]), "=r"(r[1]), "=r"(r[2]), "=r"(r[3]) : "r"(addr));
}
__device__ __forceinline__ void mma16816(float* c, const u32* a, u32 b0, u32 b1) {
    asm volatile("mma.sync.aligned.m16n8k16.row.col.f32.bf16.bf16.f32 "
        "{%0,%1,%2,%3}, {%4,%5,%6,%7}, {%8,%9}, {%0,%1,%2,%3};"
        : "+f"(c[0]), "+f"(c[1]), "+f"(c[2]), "+f"(c[3])
        : "r"(a[0]), "r"(a[1]), "r"(a[2]), "r"(a[3]), "r"(b0), "r"(b1));
}
__device__ __forceinline__ void cpasync16(u32 dst, const void* src) {
    asm volatile("cp.async.cg.shared.global [%0], [%1], 16;" :: "r"(dst), "l"(src));
}
__device__ __forceinline__ void cpcommit() {
    asm volatile("cp.async.commit_group;" ::: "memory");
}
__device__ __forceinline__ void cpwait0() {
    asm volatile("cp.async.wait_group 0;" ::: "memory");
}
__device__ __forceinline__ int f2ord(float f) {
    int i = __float_as_int(f);
    return i >= 0 ? i : i ^ 0x7FFFFFFF;
}
__device__ __forceinline__ float ord2f(int i) {
    return __int_as_float(i >= 0 ? i : i ^ 0x7FFFFFFF);
}
// unsigned monotone key for lexicographic (score, code) minimum
__device__ __forceinline__ u64 skey(float sc, int code) {
    u32 o = (u32)f2ord(sc) ^ 0x80000000u;
    return ((u64)o << 32) | (u32)code;
}

// ---------------------------------------------------------------------------
// k0: warp-per-code prep (validated ~7us).
// ---------------------------------------------------------------------------
__global__ void __launch_bounds__(128)
prep_kernel(const float* __restrict__ cb) {
    __shared__ float stage[4][264];
    __shared__ float nrm[4];
    const int t    = threadIdx.x;
    const int lane = t & 31;
    const int w    = t >> 5;
    #pragma unroll
    for (int pass = 0; pass < 2; ++pass) {
        int c = blockIdx.x * 8 + pass * 4 + w;
        const float* row = cb + (size_t)c * D;
        float4 v0[2];
        u16 pk[8];
        #pragma unroll
        for (int h = 0; h < 2; ++h) {
            v0[h] = *(const float4*)&row[lane * 8 + h * 4];
            __nv_bfloat16 b0 = __float2bfloat16(v0[h].x);
            __nv_bfloat16 b1 = __float2bfloat16(v0[h].y);
            __nv_bfloat16 b2 = __float2bfloat16(v0[h].z);
            __nv_bfloat16 b3 = __float2bfloat16(v0[h].w);
            pk[h * 4 + 0] = *(u16*)&b0; pk[h * 4 + 1] = *(u16*)&b1;
            pk[h * 4 + 2] = *(u16*)&b2; pk[h * 4 + 3] = *(u16*)&b3;
            *(float4*)&stage[w][lane * 8 + h * 4] = v0[h];
        }
        g_cbbf4[(size_t)c * 32 + lane] = *(uint4*)pk;
        __syncwarp();
        if (lane == 0) {
            float s = 0.0f;
            #pragma unroll 8
            for (int d = 0; d < D; ++d) {
                float v = stage[w][d];
                s = __fadd_rn(s, __fmul_rn(v, v));   // sequential ascending d, unfused
            }
            g_cnorm[c] = s;
            nrm[w] = (pass == 0) ? s : fmaxf(nrm[w], s);
        }
        __syncwarp();
    }
    __syncthreads();
    if (t == 0)
        atomicMax(&g_cnmax, f2ord(fmaxf(fmaxf(nrm[0], nrm[1]), fmaxf(nrm[2], nrm[3]))));
}

// ---------------------------------------------------------------------------
// k1: mma.sync bf16 GEMM + candidate filter (validated R15 form: 64-row CTA,
// 64-code B tiles, 2 CTAs/SM, register double-buffered k-loop).
// ---------------------------------------------------------------------------
__global__ void __launch_bounds__(256, 2)
mma_cand_kernel(const float* __restrict__ z) {
    extern __shared__ char smr[];
    u16*   Asm    = (u16*)smr;                            // [64][264]
    float* cn_s   = (float*)(smr + TILE_A + 2 * TILE_Bb); // [1024]
    float* marg_s = cn_s + 1024;                          // [64]
    int*   rmin_s = (int*)(marg_s + 64);                  // [64]
    int*   cnt_s  = rmin_s + 64;                          // [64]
    u16*   cand_s = (u16*)(cnt_s + 64);                   // [64][CAP]

    const int t      = threadIdx.x;
    const int lane   = t & 31;
    const int wid    = t >> 5;
    const int warp_m = wid & 1;
    const int warp_n = wid >> 1;
    const int gid    = lane >> 2;
    const int tig    = lane & 3;
    const int n0     = blockIdx.x * RTILE;

    const u32 Abase = smem_u32(Asm);
    const u32 Bbase = Abase + TILE_A;

    {   // prefetch B tile 0
        const char* src = ((const char*)g_cbbf4);
        for (int i = t; i < 2048; i += 256) {
            int r = i >> 5, c = i & 31;
            cpasync16(Bbase + (u32)(r * 528 + c * 16), src + r * 512 + c * 16);
        }
        cpcommit();
    }

    if (t < RTILE) {
        const int b  = n0 >> 10;
        const int hw = (n0 & 1023) + t;
        const float* zb = z + (size_t)b * (D * 1024) + hw;
        float s = 0.0f;
        for (int d0 = 0; d0 < D; d0 += 8) {
            u16 pk[8];
            #pragma unroll
            for (int i = 0; i < 8; ++i) {
                float v = zb[(size_t)(d0 + i) * 1024];
                s = __fadd_rn(s, __fmul_rn(v, v));      // exact sequential ascending d
                __nv_bfloat16 h = __float2bfloat16(-2.0f * v);
                pk[i] = *(u16*)&h;
            }
            *(uint4*)&Asm[t * ASTRIDE + d0] = *(uint4*)pk;
        }
        g_znorm[n0 + t] = s;
        float cm = ord2f(g_cnmax);
        marg_s[t] = 0.015625f * sqrtf(s * cm) + 3e-4f;
        rmin_s[t] = 0x7F800000;
        cnt_s[t]  = 0;
    } else {
        for (int i = t - RTILE; i < Kc; i += 256 - RTILE) cn_s[i] = g_cnorm[i];
    }

    float rm[4] = {3.4e38f, 3.4e38f, 3.4e38f, 3.4e38f};
    int   rowv[4];
    #pragma unroll
    for (int r4 = 0; r4 < 4; ++r4)
        rowv[r4] = warp_m * 32 + (r4 >> 1) * 16 + (r4 & 1) * 8 + gid;

    const int ar = warp_m * 32 + (lane & 15);
    const int ak = (lane >> 4) << 3;
    const int bc = warp_n * 16 + ((lane >> 4) & 1) * 8 + (lane & 7);
    const int bk = ((lane >> 3) & 1) * 8;

    for (int nt = 0; nt < NTILES; ++nt) {
        cpwait0();
        __syncthreads();
        if (nt < NTILES - 1) {
            const char* src = ((const char*)g_cbbf4) + (size_t)(nt + 1) * BTILE * 512;
            u32 dstb = Bbase + (u32)(((nt + 1) & 1) * TILE_Bb);
            for (int i = t; i < 2048; i += 256) {
                int r = i >> 5, c = i & 31;
                cpasync16(dstb + (u32)(r * 528 + c * 16), src + r * 512 + c * 16);
            }
            cpcommit();
        }
        const u32 Bb = Bbase + (u32)((nt & 1) * TILE_Bb);

        float acc[2][2][4];
        #pragma unroll
        for (int mt = 0; mt < 2; ++mt)
            #pragma unroll
            for (int j = 0; j < 2; ++j)
                #pragma unroll
                for (int c = 0; c < 4; ++c) acc[mt][j][c] = 0.0f;

        u32 af[2][2][4], bq[2][4];
        #pragma unroll
        for (int mt = 0; mt < 2; ++mt)
            ldsm4(af[0][mt], Abase + (u32)(((ar + mt * 16) * ASTRIDE + ak) * 2));
        ldsm4(bq[0], Bb + (u32)((bc * ASTRIDE + bk) * 2));
        #pragma unroll
        for (int kk = 0; kk < 16; ++kk) {
            const int cur = kk & 1, nxt = cur ^ 1;
            if (kk < 15) {
                int ko = (kk + 1) * 16;
                #pragma unroll
                for (int mt = 0; mt < 2; ++mt)
                    ldsm4(af[nxt][mt], Abase + (u32)(((ar + mt * 16) * ASTRIDE + ko + ak) * 2));
                ldsm4(bq[nxt], Bb + (u32)((bc * ASTRIDE + ko + bk) * 2));
            }
            #pragma unroll
            for (int mt = 0; mt < 2; ++mt) {
                mma16816(acc[mt][0], af[cur][mt], bq[cur][0], bq[cur][1]);
                mma16816(acc[mt][1], af[cur][mt], bq[cur][2], bq[cur][3]);
            }
        }

        float cnv[4];
        #pragma unroll
        for (int j = 0; j < 2; ++j) {
            int cd = nt * BTILE + warp_n * 16 + j * 8 + tig * 2;
            cnv[j * 2]     = cn_s[cd];
            cnv[j * 2 + 1] = cn_s[cd + 1];
        }
        #pragma unroll
        for (int mt = 0; mt < 2; ++mt)
            #pragma unroll
            for (int j = 0; j < 2; ++j)
                #pragma unroll
                for (int c = 0; c < 2; ++c) {
                    float g0 = cnv[j * 2 + c] + acc[mt][j][c];
                    float g1 = cnv[j * 2 + c] + acc[mt][j][2 + c];
                    rm[mt * 2]     = fminf(rm[mt * 2], g0);
                    rm[mt * 2 + 1] = fminf(rm[mt * 2 + 1], g1);
                }
        #pragma unroll
        for (int r4 = 0; r4 < 4; ++r4) {
            rm[r4] = fminf(rm[r4], __shfl_xor_sync(0xFFFFFFFF, rm[r4], 1));
            rm[r4] = fminf(rm[r4], __shfl_xor_sync(0xFFFFFFFF, rm[r4], 2));
        }
        if (tig == 0) {
            #pragma unroll
            for (int r4 = 0; r4 < 4; ++r4)
                atomicMin(&rmin_s[rowv[r4]], f2ord(rm[r4]));
        }
        float thr[4];
        #pragma unroll
        for (int r4 = 0; r4 < 4; ++r4)
            thr[r4] = fminf(rm[r4], ord2f(rmin_s[rowv[r4]])) + marg_s[rowv[r4]];

        #pragma unroll
        for (int mt = 0; mt < 2; ++mt)
            #pragma unroll
            for (int j = 0; j < 2; ++j)
                #pragma unroll
                for (int c = 0; c < 2; ++c) {
                    int code = nt * BTILE + warp_n * 16 + j * 8 + tig * 2 + c;
                    float g0 = cnv[j * 2 + c] + acc[mt][j][c];
                    float g1 = cnv[j * 2 + c] + acc[mt][j][2 + c];
                    if (g0 <= thr[mt * 2]) {
                        int row = warp_m * 32 + mt * 16 + gid;
                        int sl = atomicAdd(&cnt_s[row], 1);
                        if (sl < CAP) cand_s[row * CAP + sl] = (u16)code;
                    }
                    if (g1 <= thr[mt * 2 + 1]) {
                        int row = warp_m * 32 + mt * 16 + 8 + gid;
                        int sl = atomicAdd(&cnt_s[row], 1);
                        if (sl < CAP) cand_s[row * CAP + sl] = (u16)code;
                    }
                }
    }
    __syncthreads();

    if (t < RTILE) {
        int c = cnt_s[t];
        g_ccnt[n0 + t] = (c > CAP) ? 255 : (unsigned char)c;
    }
    for (int i = t; i < RTILE * CAP; i += 256)
        g_cand[(size_t)n0 * CAP + i] = cand_s[i];
}

// ---------------------------------------------------------------------------
// k2: fused finish with TASK-QUEUE exact verify. Tasks (row, code) collected
// block-wide; 256 threads each run one full dot chain concurrently; winners
// via u64 atomicMin on lexicographic (score, code) keys (== jnp.argmin
// first-occurrence, order-independent). Numerics per task byte-identical to
// the validated bit-exact scorer. Overflow rows (~never) get a block scan.
// ---------------------------------------------------------------------------
__global__ void __launch_bounds__(256)
finish_kernel(const float* __restrict__ z, const float* __restrict__ cb,
              float* __restrict__ out) {
    __shared__ float z_s[32][257];
    __shared__ float q_s[32][257];
    __shared__ u64   best_s[32];
    __shared__ int   win_s[32];
    __shared__ u32   tasks[32 * CAP];   // row<<16 | code
    __shared__ int   nq;
    __shared__ int   ovf_any;
    __shared__ float rs[256];

    const int t   = threadIdx.x;
    const int n0  = blockIdx.x * 32;
    const int b   = n0 >> 10;
    const int hw0 = n0 & 1023;
    const float* zb = z + (size_t)b * (D * 1024) + hw0;

    if (t == 0) { nq = 0; ovf_any = 0; }
    // stage z tile: coalesced gmem reads, conflict-free smem writes
    for (int i = t; i < 32 * 256; i += 256) {
        int d = i >> 5, j = i & 31;
        z_s[j][d] = zb[(size_t)d * 1024 + j];
    }
    __syncthreads();

    // ---- build task queue (one thread per row) ----
    if (t < 32) {
        int n   = n0 + t;
        int cnt = g_ccnt[n];
        if (cnt == 1) {
            best_s[t] = skey(-3.4e38f, g_cand[(size_t)n * CAP] & 1023);
        } else if (cnt <= CAP) {
            best_s[t] = ~0ull;
            int base = atomicAdd(&nq, cnt);
            for (int i = 0; i < cnt; ++i)
                tasks[base + i] = ((u32)t << 16) | (g_cand[(size_t)n * CAP + i] & 1023);
        } else {
            best_s[t] = ~0ull;
            atomicExch(&ovf_any, 1);
        }
    }
    __syncthreads();

    // ---- execute tasks: one dot chain per thread, fully concurrent ----
    {
        int total = nq;
        for (int i = t; i < total; i += 256) {
            u32 tk  = tasks[i];
            int r    = tk >> 16;
            int code = tk & 0xFFFF;
            const float4* cr4 = (const float4*)(cb + (size_t)code * D);
            float dot = 0.0f;
            #pragma unroll 4
            for (int d4 = 0; d4 < D / 4; ++d4) {
                float4 c4 = cr4[d4];
                int d = d4 * 4;
                dot = fmaf(z_s[r][d    ], c4.x, dot);   // sequential ascending d
                dot = fmaf(z_s[r][d + 1], c4.y, dot);
                dot = fmaf(z_s[r][d + 2], c4.z, dot);
                dot = fmaf(z_s[r][d + 3], c4.w, dot);
            }
            float t1 = __fadd_rn(g_znorm[n0 + r], g_cnorm[code]);
            float sc = __fadd_rn(t1, __fmul_rn(-2.0f, dot));
            atomicMin(&best_s[r], skey(sc, code));
        }
    }
    __syncthreads();

    // ---- overflow fallback: block-wide exact scan per overflow row ----
    if (ovf_any) {
        for (int r = 0; r < 32; ++r) {
            if (g_ccnt[n0 + r] != 255) continue;
            float zn = g_znorm[n0 + r];
            for (int code = t; code < Kc; code += 256) {
                const float4* cr4 = (const float4*)(cb + (size_t)code * D);
                float dot = 0.0f;
                #pragma unroll 4
                for (int d4 = 0; d4 < D / 4; ++d4) {
                    float4 c4 = cr4[d4];
                    int d = d4 * 4;
                    dot = fmaf(z_s[r][d    ], c4.x, dot);
                    dot = fmaf(z_s[r][d + 1], c4.y, dot);
                    dot = fmaf(z_s[r][d + 2], c4.z, dot);
                    dot = fmaf(z_s[r][d + 3], c4.w, dot);
                }
                float t1 = __fadd_rn(zn, g_cnorm[code]);
                float sc = __fadd_rn(t1, __fmul_rn(-2.0f, dot));
                atomicMin(&best_s[r], skey(sc, code));
            }
        }
        __syncthreads();
    }

    if (t < 32) {
        int bi = (int)(best_s[t] & 1023u);
        win_s[t] = bi;
        out[Z_ELEMS + n0 + t] = (float)bi;
    }
    __syncthreads();

    // ---- phase 2: gather + STE + loss ----
    for (int i = t; i < 32 * 256; i += 256) {
        int j = i >> 8, d = i & 255;
        q_s[j][d] = cb[(size_t)win_s[j] * D + d];
    }
    __syncthreads();

    float* ob = out + (size_t)b * (D * 1024) + hw0;
    float ls = 0.0f;
    #pragma unroll
    for (int it = 0; it < 8; ++it) {
        int idx = t + it * 256;
        int j4  = (idx & 7) * 4;
        int d   = idx >> 3;
        float4 zv;
        zv.x = z_s[j4    ][d];
        zv.y = z_s[j4 + 1][d];
        zv.z = z_s[j4 + 2][d];
        zv.w = z_s[j4 + 3][d];
        float4 qv;
        qv.x = q_s[j4    ][d];
        qv.y = q_s[j4 + 1][d];
        qv.z = q_s[j4 + 2][d];
        qv.w = q_s[j4 + 3][d];
        float4 ov;
        float dx = __fadd_rn(qv.x, -zv.x); ov.x = __fadd_rn(zv.x, dx);
        float dy = __fadd_rn(qv.y, -zv.y); ov.y = __fadd_rn(zv.y, dy);
        float dz = __fadd_rn(qv.z, -zv.z); ov.z = __fadd_rn(zv.z, dz);
        float dw = __fadd_rn(qv.w, -zv.w); ov.w = __fadd_rn(zv.w, dw);
        *(float4*)&ob[(size_t)d * 1024 + j4] = ov;
        ls += dx * dx + dy * dy + dz * dz + dw * dw;
    }
    rs[t] = ls;
    __syncthreads();
    #pragma unroll
    for (int s = 128; s > 0; s >>= 1) {
        if (t < s) rs[t] += rs[t + s];
        __syncthreads();
    }
    if (t == 0) {
        atomicAdd(&g_loss, rs[0]);
        __threadfence();
        unsigned tick = atomicAdd(&g_done, 1u);
        if (tick == (NROWS / 32) - 1) {
            out[Z_ELEMS + NROWS] = 1.25f * g_loss / (float)Z_ELEMS;
            g_loss = 0.0f;
            g_done = 0u;
        }
    }
}

// ---------------------------------------------------------------------------
extern "C" void kernel_launch(void* const* d_in, const int* in_sizes, int n_in,
                              void* d_out, int out_size) {
    const float* z  = (const float*)d_in[0];
    const float* cb = (const float*)d_in[1];
    float* out = (float*)d_out;

    const int mma_smem = TILE_A + 2 * TILE_Bb + 4096 + 64 * 4 * 3 + 64 * CAP * 2; // 110336

    cudaFuncSetAttribute(mma_cand_kernel,
                         cudaFuncAttributeMaxDynamicSharedMemorySize, mma_smem);

    prep_kernel<<<128, 128>>>(cb);
    mma_cand_kernel<<<NROWS / RTILE, 256, mma_smem>>>(z);
    finish_kernel<<<NROWS / 32, 256>>>(z, cb, out);
}